// round 16
// baseline (speedup 1.0000x reference)
#include <cuda_runtime.h>
#include <cuda_fp16.h>

#define NN   16384
#define EE   524288
#define FIN  128
#define FHID 256
#define FOUT 128
#define LN_EPS 1e-5f
#define CAP  96

#define HBITS 20
#define HSZ   (1u << HBITS)
#define HMASK (HSZ - 1)

typedef unsigned long long u64t;

// ---------------- static device scratch ----------------------------------------
// g_hslot: zero at module load; k_fillscan zeroes every nonzero slot after use,
// restoring the all-zero invariant for the next graph replay.
__device__ u64t   g_hslot[HSZ];
__device__ float  g_deg[NN];
__device__ int    g_cnt[NN];
__device__ float2 g_bkt[(size_t)NN * CAP];
__device__ __half g_aggh[(size_t)NN * FIN];
__device__ __half g_w1h[FIN * FHID];
__device__ __half g_w2h[FHID * FOUT];
__device__ __half2 g_xh[(size_t)NN * FIN / 2];
__device__ __half2 g_zh[(size_t)NN * FOUT / 2];

__device__ __forceinline__ unsigned hsh(unsigned k) {
    return (k * 2654435761u) >> (32 - HBITS);
}

// ---------------- insert (blocks 0..2047) + convert/init (blocks 2048..6143) ----
__global__ void k_insert_cvt(const void* __restrict__ ei, const float* __restrict__ x,
                             const float* __restrict__ W1, const float* __restrict__ W2) {
    int b = blockIdx.x;
    int tid = threadIdx.x;
    if (b < 2048) {
        __shared__ int s_is64;
        if (tid == 0) {
            const int* p = (const int*)ei;
            int o = 0;
#pragma unroll
            for (int j = 0; j < 64; j++) o |= p[2 * j + 1];
            s_is64 = (o == 0) ? 1 : 0;
        }
        __syncthreads();
        int e = b * 256 + tid;
        unsigned r, c;
        if (s_is64) {
            const long long* p = (const long long*)ei;
            r = (unsigned)p[e]; c = (unsigned)p[EE + e];
        } else {
            const int* p = (const int*)ei;
            r = (unsigned)p[e]; c = (unsigned)p[EE + e];
        }
        unsigned key = (r << 14) | c;
        u64t ins = ((u64t)key << 20) | (unsigned)(e + 1);
        unsigned h = hsh(key);
        while (true) {
            u64t old = atomicCAS(&g_hslot[h], 0ull, ins);
            if (old == 0ull) break;
            if ((unsigned)(old >> 20) == key) {
                atomicMax(&g_hslot[h], ins);
                break;
            }
            h = (h + 1) & HMASK;
        }
    } else {
        int i = (b - 2048) * 256 + tid;
        float2 v = ((const float2*)x)[i];
        g_xh[i] = __floats2half2_rn(v.x, v.y);
        if (i < FIN * FHID) {
            g_w1h[i] = __float2half_rn(__ldg(&W1[i]));
            g_w2h[i] = __float2half_rn(__ldg(&W2[i]));
        }
        if (i < NN) { g_deg[i] = 1.0f; g_cnt[i] = 0; }
    }
}

// ---------------- fillscan: consume winners, then zero slots for replay ---------
__global__ void k_fillscan(const float* __restrict__ ew) {
    unsigned i = blockIdx.x * blockDim.x + threadIdx.x;
    ulonglong2 ss = ((const ulonglong2*)g_hslot)[i];
#pragma unroll
    for (int s = 0; s < 2; s++) {
        u64t sl = (s == 0) ? ss.x : ss.y;
        if (sl == 0ull) continue;
        unsigned key = (unsigned)(sl >> 20);
        unsigned e = (unsigned)(sl & 0xFFFFFu) - 1u;
        unsigned r = key >> 14, c = key & 0x3FFFu;
        float w = __ldg(&ew[e]);
        int slot = atomicAdd(&g_cnt[r], 1);
        if (slot < CAP) {
            float2 cw; cw.x = __uint_as_float(c); cw.y = w;
            g_bkt[(size_t)r * CAP + slot] = cw;
        }
        atomicAdd(&g_deg[r], w);
        g_hslot[2 * i + s] = 0ull;
    }
}

// ---------------- SpMM (FROZEN known-good form — fp16 gather, 32 regs) ----------
__device__ __forceinline__ float4 h8_to_f4(uint2 v) {
    __half2 h0 = *(__half2*)&v.x, h1 = *(__half2*)&v.y;
    float2 f0 = __half22float2(h0), f1 = __half22float2(h1);
    return make_float4(f0.x, f0.y, f1.x, f1.y);
}

__device__ __forceinline__ float4 gather_row(const uint2* __restrict__ X,
                                             int row, int lane) {
    float4 acc = h8_to_f4(__ldg(&X[((unsigned)row << 5) + lane]));
    int n = g_cnt[row]; if (n > CAP) n = CAP;
    const float4* __restrict__ B4 = (const float4*)(g_bkt + (size_t)row * CAP);
    int t4 = n >> 2;
    for (int t = 0; t < t4; t++) {
        float4 p = __ldg(&B4[2 * t]);
        float4 q = __ldg(&B4[2 * t + 1]);
        unsigned c0 = __float_as_uint(p.x), c1 = __float_as_uint(p.z);
        unsigned c2 = __float_as_uint(q.x), c3 = __float_as_uint(q.z);
        uint2 v0 = __ldg(&X[(c0 << 5) + lane]);
        uint2 v1 = __ldg(&X[(c1 << 5) + lane]);
        uint2 v2 = __ldg(&X[(c2 << 5) + lane]);
        uint2 v3 = __ldg(&X[(c3 << 5) + lane]);
        float4 f0 = h8_to_f4(v0), f1 = h8_to_f4(v1);
        float4 f2 = h8_to_f4(v2), f3 = h8_to_f4(v3);
        acc.x += p.y * f0.x; acc.y += p.y * f0.y; acc.z += p.y * f0.z; acc.w += p.y * f0.w;
        acc.x += p.w * f1.x; acc.y += p.w * f1.y; acc.z += p.w * f1.z; acc.w += p.w * f1.w;
        acc.x += q.y * f2.x; acc.y += q.y * f2.y; acc.z += q.y * f2.z; acc.w += q.y * f2.w;
        acc.x += q.w * f3.x; acc.y += q.w * f3.y; acc.z += q.w * f3.z; acc.w += q.w * f3.w;
    }
    const float2* __restrict__ B2 = (const float2*)B4;
    for (int j = t4 * 4; j < n; j++) {
        float2 cw = __ldg(&B2[j]);
        unsigned c = __float_as_uint(cw.x);
        float4 v = h8_to_f4(__ldg(&X[(c << 5) + lane]));
        acc.x += cw.y * v.x; acc.y += cw.y * v.y;
        acc.z += cw.y * v.z; acc.w += cw.y * v.w;
    }
    return acc;
}

__global__ void k_spmm1h() {
    int g = blockIdx.x * blockDim.x + threadIdx.x;
    int row = g >> 5, lane = g & 31;
    float4 acc = gather_row((const uint2*)g_xh, row, lane);
    float inv = 1.0f / g_deg[row];
    __half2 h0 = __floats2half2_rn(acc.x * inv, acc.y * inv);
    __half2 h1 = __floats2half2_rn(acc.z * inv, acc.w * inv);
    uint2 o; o.x = *(unsigned*)&h0; o.y = *(unsigned*)&h1;
    ((uint2*)g_aggh)[((size_t)row << 5) + lane] = o;
}

__global__ void k_spmm2h(const float* __restrict__ b2, float* __restrict__ outf) {
    int g = blockIdx.x * blockDim.x + threadIdx.x;
    int row = g >> 5, lane = g & 31;
    float4 acc = gather_row((const uint2*)g_zh, row, lane);
    float inv = 1.0f / g_deg[row];
    float4 bb = ((const float4*)b2)[lane];
    acc.x = acc.x * inv + bb.x; acc.y = acc.y * inv + bb.y;
    acc.z = acc.z * inv + bb.z; acc.w = acc.w * inv + bb.w;
    ((float4*)outf)[((size_t)row << 5) + lane] = acc;
}

// ---------------- tensor-core fused GEMM: 512 threads, 16 warps, no spills ------
#define WOFF 0
#define AOFF 34816
#define SMEM_T ((34816 + 16896) * 2)   // 103,424 B

#define LDSM4(r0, r1, r2, r3, a) \
    asm volatile("ldmatrix.sync.aligned.m8n8.x4.shared.b16 {%0,%1,%2,%3}, [%4];" \
                 : "=r"(r0), "=r"(r1), "=r"(r2), "=r"(r3) : "r"(a))
#define LDSM4T(r0, r1, r2, r3, a) \
    asm volatile("ldmatrix.sync.aligned.m8n8.x4.trans.shared.b16 {%0,%1,%2,%3}, [%4];" \
                 : "=r"(r0), "=r"(r1), "=r"(r2), "=r"(r3) : "r"(a))
#define MMA16816(d, a0, a1, a2, a3, b0, b1) \
    asm volatile("mma.sync.aligned.m16n8k16.row.col.f32.f16.f16.f32 " \
                 "{%0,%1,%2,%3},{%4,%5,%6,%7},{%8,%9},{%0,%1,%2,%3};" \
                 : "+f"((d)[0]), "+f"((d)[1]), "+f"((d)[2]), "+f"((d)[3]) \
                 : "r"(a0), "r"(a1), "r"(a2), "r"(a3), "r"(b0), "r"(b1))

__device__ __forceinline__ unsigned s2u(const void* p) {
    return (unsigned)__cvta_generic_to_shared(p);
}

__global__ void __launch_bounds__(512)
k_g12t(const float* __restrict__ b1,
       const float* __restrict__ lng, const float* __restrict__ lnb) {
    extern __shared__ __half sh[];
    __shared__ float pb[3][256];
    __shared__ float sred[4][64][2];    // [wx][row][{s,q}]
    const int tid = threadIdx.x;
    const int rbase = blockIdx.x * 64;

    if (tid < 256) {
        pb[0][tid] = __ldg(&b1[tid]);
        pb[1][tid] = __ldg(&lng[tid]);
        pb[2][tid] = __ldg(&lnb[tid]);
    }

    // W1 fp16 [k=128][n=256] -> smem stride 264
    {
        const uint4* Wg = (const uint4*)g_w1h;
#pragma unroll
        for (int i = tid; i < 4096; i += 512) {
            int k = i >> 5, n8 = i & 31;
            *(uint4*)&sh[WOFF + k * 264 + n8 * 8] = __ldg(&Wg[i]);
        }
    }
    // agg tile fp16 [64][128] -> smem stride 136
    {
        const uint4* Ag = (const uint4*)(g_aggh + (size_t)rbase * FIN);
#pragma unroll
        for (int i = tid; i < 1024; i += 512) {
            int r = i >> 4, k8 = i & 15;
            *(uint4*)&sh[AOFF + r * 136 + k8 * 8] = __ldg(&Ag[i]);
        }
    }
    __syncthreads();

    const int wid = tid >> 5, lane = tid & 31;
    const int wy = wid & 3, wx = wid >> 2;       // 4 row-groups x 4 col-groups
    const int g = lane >> 2, t = lane & 3;
    const int sub = lane >> 3, rr = lane & 7;
    const int R = wy * 16;

    // ---- phase A: dA = agg @ W1, warp tile 16 x 64 (8 n8-tiles) ----
    float dA[8][4];
#pragma unroll
    for (int j = 0; j < 8; j++) { dA[j][0] = dA[j][1] = dA[j][2] = dA[j][3] = 0.f; }

    unsigned shbase = s2u(sh);
    unsigned aAdr = shbase + (unsigned)(AOFF + (R + (sub & 1) * 8 + rr) * 136 + (sub >> 1) * 8) * 2;
    unsigned bAdr = shbase + (unsigned)(WOFF + ((sub & 1) * 8 + rr) * 264 + 64 * wx + (sub >> 1) * 8) * 2;

    for (int ks = 0; ks < 8; ks++) {
        unsigned a0, a1, a2, a3;
        LDSM4(a0, a1, a2, a3, aAdr + ks * 32);
        unsigned bk = bAdr + ks * (16 * 264 * 2);
#pragma unroll
        for (int p = 0; p < 4; p++) {
            unsigned b0, b1_, b2, b3;
            LDSM4T(b0, b1_, b2, b3, bk + p * 32);
            MMA16816(dA[2 * p],     a0, a1, a2, a3, b0, b1_);
            MMA16816(dA[2 * p + 1], a0, a1, a2, a3, b2, b3);
        }
    }
    __syncthreads();

    // W2 fp16 [k=256][n=128] -> smem stride 136 (overwrites W region)
    {
        const uint4* Wg2 = (const uint4*)g_w2h;
#pragma unroll
        for (int i = tid; i < 4096; i += 512) {
            int k = i >> 4, n8 = i & 15;
            *(uint4*)&sh[WOFF + k * 136 + n8 * 8] = __ldg(&Wg2[i]);
        }
    }

    // ---- bias + LN stats (per-warp over its 64 cols, combine 4 warps) ----
    const int C = 64 * wx;
    float s1 = 0, q1 = 0, s2 = 0, q2 = 0;
#pragma unroll
    for (int j = 0; j < 8; j++) {
        int c0 = C + 8 * j + 2 * t;
        dA[j][0] += pb[0][c0];     dA[j][1] += pb[0][c0 + 1];
        dA[j][2] += pb[0][c0];     dA[j][3] += pb[0][c0 + 1];
        s1 += dA[j][0] + dA[j][1]; q1 += dA[j][0] * dA[j][0] + dA[j][1] * dA[j][1];
        s2 += dA[j][2] + dA[j][3]; q2 += dA[j][2] * dA[j][2] + dA[j][3] * dA[j][3];
    }
#pragma unroll
    for (int off = 1; off <= 2; off <<= 1) {
        s1 += __shfl_xor_sync(0xffffffffu, s1, off);
        q1 += __shfl_xor_sync(0xffffffffu, q1, off);
        s2 += __shfl_xor_sync(0xffffffffu, s2, off);
        q2 += __shfl_xor_sync(0xffffffffu, q2, off);
    }
    if (t == 0) {
        sred[wx][R + g][0] = s1;     sred[wx][R + g][1] = q1;
        sred[wx][R + g + 8][0] = s2; sred[wx][R + g + 8][1] = q2;
    }
    __syncthreads();

    float S1 = sred[0][R + g][0] + sred[1][R + g][0] + sred[2][R + g][0] + sred[3][R + g][0];
    float Q1 = sred[0][R + g][1] + sred[1][R + g][1] + sred[2][R + g][1] + sred[3][R + g][1];
    float S2 = sred[0][R + g + 8][0] + sred[1][R + g + 8][0] + sred[2][R + g + 8][0] + sred[3][R + g + 8][0];
    float Q2 = sred[0][R + g + 8][1] + sred[1][R + g + 8][1] + sred[2][R + g + 8][1] + sred[3][R + g + 8][1];
    float mu1 = S1 * (1.0f / FHID), mu2 = S2 * (1.0f / FHID);
    float rs1 = rsqrtf(Q1 * (1.0f / FHID) - mu1 * mu1 + LN_EPS);
    float rs2 = rsqrtf(Q2 * (1.0f / FHID) - mu2 * mu2 + LN_EPS);

    // normalize + relu -> h fp16 in smem [r][k=256] stride 264
#pragma unroll
    for (int j = 0; j < 8; j++) {
        int c0 = C + 8 * j + 2 * t;
        float g0 = pb[1][c0], g1v = pb[1][c0 + 1];
        float t0 = pb[2][c0], t1v = pb[2][c0 + 1];
        float o0 = fmaxf((dA[j][0] - mu1) * rs1 * g0 + t0, 0.f);
        float o1 = fmaxf((dA[j][1] - mu1) * rs1 * g1v + t1v, 0.f);
        float o2 = fmaxf((dA[j][2] - mu2) * rs2 * g0 + t0, 0.f);
        float o3 = fmaxf((dA[j][3] - mu2) * rs2 * g1v + t1v, 0.f);
        __half2 h0 = __floats2half2_rn(o0, o1);
        __half2 h1 = __floats2half2_rn(o2, o3);
        *(unsigned*)&sh[AOFF + (R + g) * 264 + c0]     = *(unsigned*)&h0;
        *(unsigned*)&sh[AOFF + (R + g + 8) * 264 + c0] = *(unsigned*)&h1;
    }
    __syncthreads();

    // ---- phase B: z = h @ W2, warp tile 16 x 32 (4 n8-tiles) ----
    float dB[4][4];
#pragma unroll
    for (int j = 0; j < 4; j++) { dB[j][0] = dB[j][1] = dB[j][2] = dB[j][3] = 0.f; }

    const int Cz = 32 * wx;
    unsigned aB = shbase + (unsigned)(AOFF + (R + (sub & 1) * 8 + rr) * 264 + (sub >> 1) * 8) * 2;
    unsigned bB = shbase + (unsigned)(WOFF + ((sub & 1) * 8 + rr) * 136 + Cz + (sub >> 1) * 8) * 2;

    for (int ks = 0; ks < 16; ks++) {
        unsigned a0, a1, a2, a3;
        LDSM4(a0, a1, a2, a3, aB + ks * 32);
        unsigned bk = bB + ks * (16 * 136 * 2);
#pragma unroll
        for (int p = 0; p < 2; p++) {
            unsigned b0, b1_, b2, b3;
            LDSM4T(b0, b1_, b2, b3, bk + p * 32);
            MMA16816(dB[2 * p],     a0, a1, a2, a3, b0, b1_);
            MMA16816(dB[2 * p + 1], a0, a1, a2, a3, b2, b3);
        }
    }

    unsigned* Z = (unsigned*)g_zh;
#pragma unroll
    for (int j = 0; j < 4; j++) {
        int c0 = Cz + 8 * j + 2 * t;
        __half2 z0 = __floats2half2_rn(dB[j][0], dB[j][1]);
        __half2 z1 = __floats2half2_rn(dB[j][2], dB[j][3]);
        Z[(size_t)(rbase + R + g) * 64 + (c0 >> 1)]     = *(unsigned*)&z0;
        Z[(size_t)(rbase + R + g + 8) * 64 + (c0 >> 1)] = *(unsigned*)&z1;
    }
}

// ---------------- launch --------------------------------------------------------
extern "C" void kernel_launch(void* const* d_in, const int* in_sizes, int n_in,
                              void* d_out, int out_size) {
    const float* x   = (const float*)d_in[0];
    const void*  ei  = d_in[1];
    const float* ew  = (const float*)d_in[2];
    const float* W1  = (const float*)d_in[3];
    const float* b1  = (const float*)d_in[4];
    const float* W2  = (const float*)d_in[5];
    const float* b2  = (const float*)d_in[6];
    const float* lng = (const float*)d_in[7];
    const float* lnb = (const float*)d_in[8];
    float* out = (float*)d_out;

    cudaFuncSetAttribute(k_g12t, cudaFuncAttributeMaxDynamicSharedMemorySize, SMEM_T);

    k_insert_cvt<<<2048 + 4096, 256>>>(ei, x, W1, W2);
    k_fillscan<<<HSZ / 512, 256>>>(ew);
    k_spmm1h<<<(NN * 32) / 256, 256>>>();
    k_g12t<<<NN / 64, 512, SMEM_T>>>(b1, lng, lnb);
    k_spmm2h<<<(NN * 32) / 256, 256>>>(b2, out);
}

// round 17
// speedup vs baseline: 1.0251x; 1.0251x over previous
#include <cuda_runtime.h>
#include <cuda_fp16.h>

#define NN   16384
#define EE   524288
#define FIN  128
#define FHID 256
#define FOUT 128
#define LN_EPS 1e-5f
#define CAP  96

#define HBITS 20
#define HSZ   (1u << HBITS)
#define HMASK (HSZ - 1)

typedef unsigned long long u64t;

// ---------------- static device scratch ----------------------------------------
// g_hslot: zero at module load; k_fillscan zeroes every nonzero slot after use,
// restoring the all-zero invariant for the next graph replay.
__device__ u64t   g_hslot[HSZ];
__device__ float  g_deg[NN];
__device__ int    g_cnt[NN];
__device__ float2 g_bkt[(size_t)NN * CAP];
__device__ __half g_aggh[(size_t)NN * FIN];
__device__ __half g_w1h[FIN * FHID];
__device__ __half g_w2h[FHID * FOUT];
__device__ __half2 g_xh[(size_t)NN * FIN / 2];
__device__ __half2 g_zh[(size_t)NN * FOUT / 2];

__device__ __forceinline__ unsigned hsh(unsigned k) {
    return (k * 2654435761u) >> (32 - HBITS);
}

// ---------------- insert (blocks 0..2047) + convert/init (blocks 2048..6143) ----
__global__ void k_insert_cvt(const void* __restrict__ ei, const float* __restrict__ x,
                             const float* __restrict__ W1, const float* __restrict__ W2) {
    int b = blockIdx.x;
    int tid = threadIdx.x;
    if (b < 2048) {
        __shared__ int s_is64;
        if (tid == 0) {
            const int* p = (const int*)ei;
            int o = 0;
#pragma unroll
            for (int j = 0; j < 64; j++) o |= p[2 * j + 1];
            s_is64 = (o == 0) ? 1 : 0;
        }
        __syncthreads();
        int e = b * 256 + tid;
        unsigned r, c;
        if (s_is64) {
            const long long* p = (const long long*)ei;
            r = (unsigned)p[e]; c = (unsigned)p[EE + e];
        } else {
            const int* p = (const int*)ei;
            r = (unsigned)p[e]; c = (unsigned)p[EE + e];
        }
        unsigned key = (r << 14) | c;
        u64t ins = ((u64t)key << 20) | (unsigned)(e + 1);
        unsigned h = hsh(key);
        while (true) {
            u64t old = atomicCAS(&g_hslot[h], 0ull, ins);
            if (old == 0ull) break;
            if ((unsigned)(old >> 20) == key) {
                atomicMax(&g_hslot[h], ins);
                break;
            }
            h = (h + 1) & HMASK;
        }
    } else {
        int i = (b - 2048) * 256 + tid;
        float2 v = ((const float2*)x)[i];
        g_xh[i] = __floats2half2_rn(v.x, v.y);
        if (i < FIN * FHID) {
            g_w1h[i] = __float2half_rn(__ldg(&W1[i]));
            g_w2h[i] = __float2half_rn(__ldg(&W2[i]));
        }
        if (i < NN) { g_deg[i] = 1.0f; g_cnt[i] = 0; }
    }
}

// ---------------- fillscan: consume winners, then zero slots for replay ---------
__global__ void k_fillscan(const float* __restrict__ ew) {
    unsigned i = blockIdx.x * blockDim.x + threadIdx.x;
    ulonglong2 ss = ((const ulonglong2*)g_hslot)[i];
#pragma unroll
    for (int s = 0; s < 2; s++) {
        u64t sl = (s == 0) ? ss.x : ss.y;
        if (sl == 0ull) continue;
        unsigned key = (unsigned)(sl >> 20);
        unsigned e = (unsigned)(sl & 0xFFFFFu) - 1u;
        unsigned r = key >> 14, c = key & 0x3FFFu;
        float w = __ldg(&ew[e]);
        int slot = atomicAdd(&g_cnt[r], 1);
        if (slot < CAP) {
            float2 cw; cw.x = __uint_as_float(c); cw.y = w;
            g_bkt[(size_t)r * CAP + slot] = cw;
        }
        atomicAdd(&g_deg[r], w);
        g_hslot[2 * i + s] = 0ull;
    }
}

// ---------------- SpMM (FROZEN known-good form — fp16 gather, 32 regs) ----------
__device__ __forceinline__ float4 h8_to_f4(uint2 v) {
    __half2 h0 = *(__half2*)&v.x, h1 = *(__half2*)&v.y;
    float2 f0 = __half22float2(h0), f1 = __half22float2(h1);
    return make_float4(f0.x, f0.y, f1.x, f1.y);
}

__device__ __forceinline__ float4 gather_row(const uint2* __restrict__ X,
                                             int row, int lane) {
    float4 acc = h8_to_f4(__ldg(&X[((unsigned)row << 5) + lane]));
    int n = g_cnt[row]; if (n > CAP) n = CAP;
    const float4* __restrict__ B4 = (const float4*)(g_bkt + (size_t)row * CAP);
    int t4 = n >> 2;
    for (int t = 0; t < t4; t++) {
        float4 p = __ldg(&B4[2 * t]);
        float4 q = __ldg(&B4[2 * t + 1]);
        unsigned c0 = __float_as_uint(p.x), c1 = __float_as_uint(p.z);
        unsigned c2 = __float_as_uint(q.x), c3 = __float_as_uint(q.z);
        uint2 v0 = __ldg(&X[(c0 << 5) + lane]);
        uint2 v1 = __ldg(&X[(c1 << 5) + lane]);
        uint2 v2 = __ldg(&X[(c2 << 5) + lane]);
        uint2 v3 = __ldg(&X[(c3 << 5) + lane]);
        float4 f0 = h8_to_f4(v0), f1 = h8_to_f4(v1);
        float4 f2 = h8_to_f4(v2), f3 = h8_to_f4(v3);
        acc.x += p.y * f0.x; acc.y += p.y * f0.y; acc.z += p.y * f0.z; acc.w += p.y * f0.w;
        acc.x += p.w * f1.x; acc.y += p.w * f1.y; acc.z += p.w * f1.z; acc.w += p.w * f1.w;
        acc.x += q.y * f2.x; acc.y += q.y * f2.y; acc.z += q.y * f2.z; acc.w += q.y * f2.w;
        acc.x += q.w * f3.x; acc.y += q.w * f3.y; acc.z += q.w * f3.z; acc.w += q.w * f3.w;
    }
    const float2* __restrict__ B2 = (const float2*)B4;
    for (int j = t4 * 4; j < n; j++) {
        float2 cw = __ldg(&B2[j]);
        unsigned c = __float_as_uint(cw.x);
        float4 v = h8_to_f4(__ldg(&X[(c << 5) + lane]));
        acc.x += cw.y * v.x; acc.y += cw.y * v.y;
        acc.z += cw.y * v.z; acc.w += cw.y * v.w;
    }
    return acc;
}

__global__ void k_spmm1h() {
    int g = blockIdx.x * blockDim.x + threadIdx.x;
    int row = g >> 5, lane = g & 31;
    float4 acc = gather_row((const uint2*)g_xh, row, lane);
    float inv = 1.0f / g_deg[row];
    __half2 h0 = __floats2half2_rn(acc.x * inv, acc.y * inv);
    __half2 h1 = __floats2half2_rn(acc.z * inv, acc.w * inv);
    uint2 o; o.x = *(unsigned*)&h0; o.y = *(unsigned*)&h1;
    ((uint2*)g_aggh)[((size_t)row << 5) + lane] = o;
}

__global__ void k_spmm2h(const float* __restrict__ b2, float* __restrict__ outf) {
    int g = blockIdx.x * blockDim.x + threadIdx.x;
    int row = g >> 5, lane = g & 31;
    float4 acc = gather_row((const uint2*)g_zh, row, lane);
    float inv = 1.0f / g_deg[row];
    float4 bb = ((const float4*)b2)[lane];
    acc.x = acc.x * inv + bb.x; acc.y = acc.y * inv + bb.y;
    acc.z = acc.z * inv + bb.z; acc.w = acc.w * inv + bb.w;
    ((float4*)outf)[((size_t)row << 5) + lane] = acc;
}

// ---------------- tensor-core fused GEMM: 128 rows/block, 32-row warp tiles -----
// smem halfs: [WOFF: W1 [k=128][n=256+8] (33792) | W2 [k=256][n=128+8] (34816)]
//             [AOFF: agg [r=128][k=128+8] (17408) | h [r=128][k=256+8] (33792)]
#define WOFF 0
#define AOFF 34816
#define SMEM_T ((34816 + 33792) * 2)   // 137,216 B

#define LDSM4(r0, r1, r2, r3, a) \
    asm volatile("ldmatrix.sync.aligned.m8n8.x4.shared.b16 {%0,%1,%2,%3}, [%4];" \
                 : "=r"(r0), "=r"(r1), "=r"(r2), "=r"(r3) : "r"(a))
#define LDSM4T(r0, r1, r2, r3, a) \
    asm volatile("ldmatrix.sync.aligned.m8n8.x4.trans.shared.b16 {%0,%1,%2,%3}, [%4];" \
                 : "=r"(r0), "=r"(r1), "=r"(r2), "=r"(r3) : "r"(a))
#define MMA16816(d, a0, a1, a2, a3, b0, b1) \
    asm volatile("mma.sync.aligned.m16n8k16.row.col.f32.f16.f16.f32 " \
                 "{%0,%1,%2,%3},{%4,%5,%6,%7},{%8,%9},{%0,%1,%2,%3};" \
                 : "+f"((d)[0]), "+f"((d)[1]), "+f"((d)[2]), "+f"((d)[3]) \
                 : "r"(a0), "r"(a1), "r"(a2), "r"(a3), "r"(b0), "r"(b1))

__device__ __forceinline__ unsigned s2u(const void* p) {
    return (unsigned)__cvta_generic_to_shared(p);
}

__global__ void __launch_bounds__(512)
k_g12t(const float* __restrict__ b1,
       const float* __restrict__ lng, const float* __restrict__ lnb) {
    extern __shared__ __half sh[];
    __shared__ float pb[3][256];
    __shared__ float sred[4][128][2];    // [wx][row][{s,q}]
    const int tid = threadIdx.x;
    const int rbase = blockIdx.x * 128;

    if (tid < 256) {
        pb[0][tid] = __ldg(&b1[tid]);
        pb[1][tid] = __ldg(&lng[tid]);
        pb[2][tid] = __ldg(&lnb[tid]);
    }

    // W1 fp16 [k=128][n=256] -> smem stride 264
    {
        const uint4* Wg = (const uint4*)g_w1h;
#pragma unroll
        for (int i = tid; i < 4096; i += 512) {
            int k = i >> 5, n8 = i & 31;
            *(uint4*)&sh[WOFF + k * 264 + n8 * 8] = __ldg(&Wg[i]);
        }
    }
    // agg tile fp16 [128][128] -> smem stride 136
    {
        const uint4* Ag = (const uint4*)(g_aggh + (size_t)rbase * FIN);
#pragma unroll
        for (int i = tid; i < 2048; i += 512) {
            int r = i >> 4, k8 = i & 15;
            *(uint4*)&sh[AOFF + r * 136 + k8 * 8] = __ldg(&Ag[i]);
        }
    }
    __syncthreads();

    const int wid = tid >> 5, lane = tid & 31;
    const int wy = wid & 3, wx = wid >> 2;       // 4 row-groups (32 rows) x 4 col-groups
    const int g = lane >> 2, t = lane & 3;
    const int sub = lane >> 3, rr = lane & 7;
    const int R = wy * 32;

    // ---- phase A: dA = agg @ W1, warp tile 32 x 64 ----
    float dA[2][8][4];
#pragma unroll
    for (int a = 0; a < 2; a++)
#pragma unroll
        for (int j = 0; j < 8; j++) { dA[a][j][0] = dA[a][j][1] = dA[a][j][2] = dA[a][j][3] = 0.f; }

    unsigned shbase = s2u(sh);
    unsigned aAdr = shbase + (unsigned)(AOFF + (R + (sub & 1) * 8 + rr) * 136 + (sub >> 1) * 8) * 2;
    unsigned bAdr = shbase + (unsigned)(WOFF + ((sub & 1) * 8 + rr) * 264 + 64 * wx + (sub >> 1) * 8) * 2;

    for (int ks = 0; ks < 8; ks++) {
        unsigned a00, a01, a02, a03, a10, a11, a12, a13;
        LDSM4(a00, a01, a02, a03, aAdr + ks * 32);                   // rows R..R+16
        LDSM4(a10, a11, a12, a13, aAdr + 16 * 136 * 2 + ks * 32);    // rows R+16..R+32
        unsigned bk = bAdr + ks * (16 * 264 * 2);
#pragma unroll
        for (int p = 0; p < 4; p++) {
            unsigned b0, b1_, b2, b3;
            LDSM4T(b0, b1_, b2, b3, bk + p * 32);
            MMA16816(dA[0][2 * p],     a00, a01, a02, a03, b0, b1_);
            MMA16816(dA[0][2 * p + 1], a00, a01, a02, a03, b2, b3);
            MMA16816(dA[1][2 * p],     a10, a11, a12, a13, b0, b1_);
            MMA16816(dA[1][2 * p + 1], a10, a11, a12, a13, b2, b3);
        }
    }
    __syncthreads();

    // W2 fp16 [k=256][n=128] -> smem stride 136 (overwrites W region)
    {
        const uint4* Wg2 = (const uint4*)g_w2h;
#pragma unroll
        for (int i = tid; i < 4096; i += 512) {
            int k = i >> 4, n8 = i & 15;
            *(uint4*)&sh[WOFF + k * 136 + n8 * 8] = __ldg(&Wg2[i]);
        }
    }

    // ---- bias + LN stats (each lane owns 4 rows: a*16 + {g, g+8}) ----
    const int C = 64 * wx;
#pragma unroll
    for (int a = 0; a < 2; a++) {
        float s1 = 0, q1 = 0, s2 = 0, q2 = 0;
#pragma unroll
        for (int j = 0; j < 8; j++) {
            int c0 = C + 8 * j + 2 * t;
            dA[a][j][0] += pb[0][c0];     dA[a][j][1] += pb[0][c0 + 1];
            dA[a][j][2] += pb[0][c0];     dA[a][j][3] += pb[0][c0 + 1];
            s1 += dA[a][j][0] + dA[a][j][1];
            q1 += dA[a][j][0] * dA[a][j][0] + dA[a][j][1] * dA[a][j][1];
            s2 += dA[a][j][2] + dA[a][j][3];
            q2 += dA[a][j][2] * dA[a][j][2] + dA[a][j][3] * dA[a][j][3];
        }
#pragma unroll
        for (int off = 1; off <= 2; off <<= 1) {
            s1 += __shfl_xor_sync(0xffffffffu, s1, off);
            q1 += __shfl_xor_sync(0xffffffffu, q1, off);
            s2 += __shfl_xor_sync(0xffffffffu, s2, off);
            q2 += __shfl_xor_sync(0xffffffffu, q2, off);
        }
        if (t == 0) {
            sred[wx][R + a * 16 + g][0] = s1;     sred[wx][R + a * 16 + g][1] = q1;
            sred[wx][R + a * 16 + g + 8][0] = s2; sred[wx][R + a * 16 + g + 8][1] = q2;
        }
    }
    __syncthreads();

#pragma unroll
    for (int a = 0; a < 2; a++) {
        int r1 = R + a * 16 + g, r2 = r1 + 8;
        float S1 = sred[0][r1][0] + sred[1][r1][0] + sred[2][r1][0] + sred[3][r1][0];
        float Q1 = sred[0][r1][1] + sred[1][r1][1] + sred[2][r1][1] + sred[3][r1][1];
        float S2 = sred[0][r2][0] + sred[1][r2][0] + sred[2][r2][0] + sred[3][r2][0];
        float Q2 = sred[0][r2][1] + sred[1][r2][1] + sred[2][r2][1] + sred[3][r2][1];
        float mu1 = S1 * (1.0f / FHID), mu2 = S2 * (1.0f / FHID);
        float rs1 = rsqrtf(Q1 * (1.0f / FHID) - mu1 * mu1 + LN_EPS);
        float rs2 = rsqrtf(Q2 * (1.0f / FHID) - mu2 * mu2 + LN_EPS);
#pragma unroll
        for (int j = 0; j < 8; j++) {
            int c0 = C + 8 * j + 2 * t;
            float g0 = pb[1][c0], g1v = pb[1][c0 + 1];
            float t0 = pb[2][c0], t1v = pb[2][c0 + 1];
            float o0 = fmaxf((dA[a][j][0] - mu1) * rs1 * g0 + t0, 0.f);
            float o1 = fmaxf((dA[a][j][1] - mu1) * rs1 * g1v + t1v, 0.f);
            float o2 = fmaxf((dA[a][j][2] - mu2) * rs2 * g0 + t0, 0.f);
            float o3 = fmaxf((dA[a][j][3] - mu2) * rs2 * g1v + t1v, 0.f);
            __half2 h0 = __floats2half2_rn(o0, o1);
            __half2 h1 = __floats2half2_rn(o2, o3);
            *(unsigned*)&sh[AOFF + r1 * 264 + c0] = *(unsigned*)&h0;
            *(unsigned*)&sh[AOFF + r2 * 264 + c0] = *(unsigned*)&h1;
        }
    }
    __syncthreads();

    // ---- phase B: z = h @ W2, warp tile 32 x 32 ----
    float dB[2][4][4];
#pragma unroll
    for (int a = 0; a < 2; a++)
#pragma unroll
        for (int j = 0; j < 4; j++) { dB[a][j][0] = dB[a][j][1] = dB[a][j][2] = dB[a][j][3] = 0.f; }

    const int Cz = 32 * wx;
    unsigned aB = shbase + (unsigned)(AOFF + (R + (sub & 1) * 8 + rr) * 264 + (sub >> 1) * 8) * 2;
    unsigned bB = shbase + (unsigned)(WOFF + ((sub & 1) * 8 + rr) * 136 + Cz + (sub >> 1) * 8) * 2;

    for (int ks = 0; ks < 16; ks++) {
        unsigned a00, a01, a02, a03, a10, a11, a12, a13;
        LDSM4(a00, a01, a02, a03, aB + ks * 32);
        LDSM4(a10, a11, a12, a13, aB + 16 * 264 * 2 + ks * 32);
        unsigned bk = bB + ks * (16 * 136 * 2);
#pragma unroll
        for (int p = 0; p < 2; p++) {
            unsigned b0, b1_, b2, b3;
            LDSM4T(b0, b1_, b2, b3, bk + p * 32);
            MMA16816(dB[0][2 * p],     a00, a01, a02, a03, b0, b1_);
            MMA16816(dB[0][2 * p + 1], a00, a01, a02, a03, b2, b3);
            MMA16816(dB[1][2 * p],     a10, a11, a12, a13, b0, b1_);
            MMA16816(dB[1][2 * p + 1], a10, a11, a12, a13, b2, b3);
        }
    }

    unsigned* Z = (unsigned*)g_zh;
#pragma unroll
    for (int a = 0; a < 2; a++) {
#pragma unroll
        for (int j = 0; j < 4; j++) {
            int c0 = Cz + 8 * j + 2 * t;
            __half2 z0 = __floats2half2_rn(dB[a][j][0], dB[a][j][1]);
            __half2 z1 = __floats2half2_rn(dB[a][j][2], dB[a][j][3]);
            Z[(size_t)(rbase + R + a * 16 + g) * 64 + (c0 >> 1)]     = *(unsigned*)&z0;
            Z[(size_t)(rbase + R + a * 16 + g + 8) * 64 + (c0 >> 1)] = *(unsigned*)&z1;
        }
    }
}

// ---------------- launch --------------------------------------------------------
extern "C" void kernel_launch(void* const* d_in, const int* in_sizes, int n_in,
                              void* d_out, int out_size) {
    const float* x   = (const float*)d_in[0];
    const void*  ei  = d_in[1];
    const float* ew  = (const float*)d_in[2];
    const float* W1  = (const float*)d_in[3];
    const float* b1  = (const float*)d_in[4];
    const float* W2  = (const float*)d_in[5];
    const float* b2  = (const float*)d_in[6];
    const float* lng = (const float*)d_in[7];
    const float* lnb = (const float*)d_in[8];
    float* out = (float*)d_out;

    cudaFuncSetAttribute(k_g12t, cudaFuncAttributeMaxDynamicSharedMemorySize, SMEM_T);

    k_insert_cvt<<<2048 + 4096, 256>>>(ei, x, W1, W2);
    k_fillscan<<<HSZ / 512, 256>>>(ew);
    k_spmm1h<<<(NN * 32) / 256, 256>>>();
    k_g12t<<<NN / 128, 512, SMEM_T>>>(b1, lng, lnb);
    k_spmm2h<<<(NN * 32) / 256, 256>>>(b2, out);
}